// round 12
// baseline (speedup 1.0000x reference)
#include <cuda_runtime.h>

#define HID 128
#define VOCAB 28
#define N_NODES_MAX 100000
#define N_EDGES_MAX 1600000
#define NT 256

// ---- device scratch (no allocations allowed) ----
// Packed per-node histogram: 8 uint32 per node = one 32B sector.
// INVARIANT: all-zero at launch entry (zero-init at load; node phase re-zeroes).
__device__ __align__(16) unsigned g_cntp[N_NODES_MAX * 8];   // 3.2 MB
__device__ unsigned g_xid8w[(N_NODES_MAX + 3) / 4];  // xidx as packed u8
__device__ float g_Ep[VOCAB * HID];     // embed @ (w1_0 @ w2_0)
__device__ float g_b0c[HID];            // b1_0 @ w2_0 + b2_0
__device__ float g_Wc[HID];             // w1_1 @ w2_1
__device__ float g_scal[3];             // {1+eps0, 1+eps1, b1_1.w2_1 + b2_1}
__device__ float g_z1[N_NODES_MAX];     // relu(h0) . Wc per node
__device__ float g_xfall[N_NODES_MAX];  // fallback x buffer
// grid barrier state (generation counting; replay-safe)
__device__ unsigned g_bar = 0;
__device__ volatile unsigned g_gen = 0;

__global__ void __launch_bounds__(NT, 4)
k_main(const int* __restrict__ xidx, const int* __restrict__ src,
       const int* __restrict__ dst,  const int* __restrict__ batch,
       const float* __restrict__ embed, const float* __restrict__ w1_0,
       const float* __restrict__ b1_0,  const float* __restrict__ w2_0,
       const float* __restrict__ b2_0,  const float* __restrict__ w1_1,
       const float* __restrict__ b1_1,  const float* __restrict__ w2_1,
       const float* __restrict__ b2_1,  const float* __restrict__ eps0,
       const float* __restrict__ eps1,
       float* __restrict__ y_out, float* __restrict__ x_out,
       int y_len, int n_nodes, int n_edges)
{
    __shared__ __align__(16) float sEp[VOCAB * HID];
    __shared__ __align__(16) float sB[HID];
    __shared__ __align__(16) float sW[HID];
    __shared__ float sT[HID];
    __shared__ unsigned s_gen0;

    const int bid = blockIdx.x, tid = threadIdx.x;
    const int nb = gridDim.x;
    const int gsz = nb * NT;
    const int lane = tid & 31;

    if (tid == 0) s_gen0 = g_gen;   // read BEFORE any barrier can release (all
    __syncthreads();                // blocks must arrive at bar1 first)

    // ================= PHASE 0: compress xidx + fold weights + zero y =======
    {
        int nw = (n_nodes + 3) >> 2;
        for (int i = bid * NT + tid; i < nw; i += gsz) {
            unsigned p;
            int base = i << 2;
            if (base + 3 < n_nodes) {
                int4 v = ((const int4*)xidx)[i];
                p = (unsigned)(v.x & 255) | ((unsigned)(v.y & 255) << 8)
                  | ((unsigned)(v.z & 255) << 16) | ((unsigned)(v.w & 255) << 24);
            } else {
                p = 0u;
                for (int k = 0; k < 4; k++)
                    if (base + k < n_nodes) p |= (unsigned)(xidx[base + k] & 255) << (8 * k);
            }
            __stcg(&g_xid8w[i], p);   // no L1 allocate: cross-SM line sharing safe
        }
    }
    if (bid < VOCAB) {
        int j = tid;
        if (j < HID) {
            float a0 = 0.f, a1 = 0.f, a2 = 0.f, a3 = 0.f;
            #pragma unroll
            for (int m = 0; m < HID; m += 4) {
                a0 = fmaf(embed[bid * HID + m + 0], w1_0[(m + 0) * HID + j], a0);
                a1 = fmaf(embed[bid * HID + m + 1], w1_0[(m + 1) * HID + j], a1);
                a2 = fmaf(embed[bid * HID + m + 2], w1_0[(m + 2) * HID + j], a2);
                a3 = fmaf(embed[bid * HID + m + 3], w1_0[(m + 3) * HID + j], a3);
            }
            sT[j] = (a0 + a1) + (a2 + a3);
        }
        __syncthreads();
        if (j < HID) {
            float c0 = 0.f, c1 = 0.f, c2 = 0.f, c3 = 0.f;
            #pragma unroll
            for (int k = 0; k < HID; k += 4) {
                c0 = fmaf(sT[k + 0], w2_0[(k + 0) * HID + j], c0);
                c1 = fmaf(sT[k + 1], w2_0[(k + 1) * HID + j], c1);
                c2 = fmaf(sT[k + 2], w2_0[(k + 2) * HID + j], c2);
                c3 = fmaf(sT[k + 3], w2_0[(k + 3) * HID + j], c3);
            }
            g_Ep[bid * HID + j] = (c0 + c1) + (c2 + c3);   // lines fully covered
        }
    } else if (bid == VOCAB) {
        int j = tid;
        if (j < HID) {
            float c0 = b2_0[j], c1 = 0.f, c2 = 0.f, c3 = 0.f;
            #pragma unroll
            for (int k = 0; k < HID; k += 4) {
                c0 = fmaf(b1_0[k + 0], w2_0[(k + 0) * HID + j], c0);
                c1 = fmaf(b1_0[k + 1], w2_0[(k + 1) * HID + j], c1);
                c2 = fmaf(b1_0[k + 2], w2_0[(k + 2) * HID + j], c2);
                c3 = fmaf(b1_0[k + 3], w2_0[(k + 3) * HID + j], c3);
            }
            g_b0c[j] = (c0 + c1) + (c2 + c3);
        }
    } else if (bid == VOCAB + 1) {
        int j = tid;
        if (j < HID) {
            float c0 = 0.f, c1 = 0.f, c2 = 0.f, c3 = 0.f;
            #pragma unroll
            for (int k = 0; k < HID; k += 4) {
                c0 = fmaf(w1_1[j * HID + k + 0], w2_1[k + 0], c0);
                c1 = fmaf(w1_1[j * HID + k + 1], w2_1[k + 1], c1);
                c2 = fmaf(w1_1[j * HID + k + 2], w2_1[k + 2], c2);
                c3 = fmaf(w1_1[j * HID + k + 3], w2_1[k + 3], c3);
            }
            g_Wc[j] = (c0 + c1) + (c2 + c3);
        }
    } else if (bid == VOCAB + 2) {
        if (tid == 0) {
            float bc = b2_1[0];
            for (int jj = 0; jj < HID; jj++) bc = fmaf(b1_1[jj], w2_1[jj], bc);
            g_scal[0] = 1.f + eps0[0];
            g_scal[1] = 1.f + eps1[0];
            g_scal[2] = bc;
        }
    } else if (bid == VOCAB + 3) {
        for (int i = tid; i < y_len; i += NT) y_out[i] = 0.f;
    }

    // ---- grid barrier (generation counting; all 256 threads call) ----
    #define GSYNC(PHASE)                                                      \
    do {                                                                      \
        __syncthreads();                                                      \
        if (tid == 0) {                                                       \
            __threadfence();                                                  \
            if (atomicAdd(&g_bar, 1u) == (unsigned)(nb - 1)) {                \
                g_bar = 0u;                                                   \
                __threadfence();                                              \
                g_gen = s_gen0 + (PHASE);                                     \
            } else {                                                          \
                while ((unsigned)(g_gen - s_gen0) < (unsigned)(PHASE))        \
                    __nanosleep(64);                                          \
            }                                                                 \
        }                                                                     \
        __syncthreads();                                                      \
    } while (0)

    GSYNC(1);

    // ================= PHASE 1: edge histogram =============================
    {
        const unsigned char* xb = (const unsigned char*)g_xid8w;
        int n4 = n_edges >> 2;
        for (int i = bid * NT + tid; i < n4; i += gsz) {
            int4 s = ((const int4*)src)[i];
            int4 d = ((const int4*)dst)[i];
            int t0 = xb[s.x], t1 = xb[s.y], t2 = xb[s.z], t3 = xb[s.w];
            atomicAdd(&g_cntp[d.x * 8 + (t0 >> 2)], 1u << ((t0 & 3) * 8));
            atomicAdd(&g_cntp[d.y * 8 + (t1 >> 2)], 1u << ((t1 & 3) * 8));
            atomicAdd(&g_cntp[d.z * 8 + (t2 >> 2)], 1u << ((t2 & 3) * 8));
            atomicAdd(&g_cntp[d.w * 8 + (t3 >> 2)], 1u << ((t3 & 3) * 8));
        }
        int e = (n4 << 2) + bid * NT + tid;
        if (e < n_edges) {
            int t = xb[src[e]];
            atomicAdd(&g_cntp[dst[e] * 8 + (t >> 2)], 1u << ((t & 3) * 8));
        }
    }

    GSYNC(2);

    // ================= PHASE 2: node transform (warp per node) =============
    {
        for (int i = tid; i < VOCAB * HID; i += NT) sEp[i] = g_Ep[i];
        if (tid < HID) { sB[tid] = g_b0c[tid]; sW[tid] = g_Wc[tid]; }
        __syncthreads();

        const unsigned char* xb = (const unsigned char*)g_xid8w;
        float eps0p = g_scal[0], eps1p = g_scal[1], bc = g_scal[2];
        int j0 = lane * 4;
        float4 w4 = *(const float4*)&sW[j0];
        float4 b4 = *(const float4*)&sB[j0];
        int wglob = bid * 8 + (tid >> 5);
        int wstride = nb * 8;

        for (int node = wglob; node < n_nodes; node += wstride) {
            unsigned w = 0;
            if (lane < 8) {
                w = g_cntp[node * 8 + lane];     // atomics don't populate L1: fresh
                g_cntp[node * 8 + lane] = 0u;    // restore invariant for replay
            }
            int tn = xb[node];
            float4 acc = b4;
            {
                float4 e4 = *(const float4*)&sEp[tn * HID + j0];
                acc.x = fmaf(eps0p, e4.x, acc.x); acc.y = fmaf(eps0p, e4.y, acc.y);
                acc.z = fmaf(eps0p, e4.z, acc.z); acc.w = fmaf(eps0p, e4.w, acc.w);
            }
            #pragma unroll
            for (int t = 0; t < VOCAB; t++) {
                unsigned wt = __shfl_sync(0xffffffffu, w, t >> 2);
                unsigned ct = (wt >> ((t & 3) * 8)) & 255u;
                if (ct) {                        // warp-uniform
                    float f = (float)ct;
                    float4 e4 = *(const float4*)&sEp[t * HID + j0];
                    acc.x = fmaf(f, e4.x, acc.x); acc.y = fmaf(f, e4.y, acc.y);
                    acc.z = fmaf(f, e4.z, acc.z); acc.w = fmaf(f, e4.w, acc.w);
                }
            }
            float s = fmaxf(acc.x, 0.f) * w4.x + fmaxf(acc.y, 0.f) * w4.y
                    + fmaxf(acc.z, 0.f) * w4.z + fmaxf(acc.w, 0.f) * w4.w;
            #pragma unroll
            for (int o = 16; o > 0; o >>= 1) s += __shfl_xor_sync(0xffffffffu, s, o);
            if (lane == 0) {
                __stcg(&g_z1[node], s);                      // no L1 allocate
                __stcg(&x_out[node], fmaf(eps1p, s, bc));    // scatter adds on top
            }
        }
    }

    GSYNC(3);

    // ================= PHASE 3: scalar scatter =============================
    {
        int n4 = n_edges >> 2;
        for (int i = bid * NT + tid; i < n4; i += gsz) {
            int4 s = ((const int4*)src)[i];
            int4 d = ((const int4*)dst)[i];
            float z0 = g_z1[s.x], z1v = g_z1[s.y], z2 = g_z1[s.z], z3 = g_z1[s.w];
            atomicAdd(&x_out[d.x], z0);
            atomicAdd(&x_out[d.y], z1v);
            atomicAdd(&x_out[d.z], z2);
            atomicAdd(&x_out[d.w], z3);
        }
        int e = (n4 << 2) + bid * NT + tid;
        if (e < n_edges) atomicAdd(&x_out[dst[e]], g_z1[src[e]]);
    }

    GSYNC(4);

    // ================= PHASE 4: graph readout ==============================
    for (int n0 = bid * NT; n0 < n_nodes; n0 += gsz) {
        int n = n0 + tid;
        float v = 0.f;
        int g = -1;
        if (n < n_nodes) { v = __ldcg(&x_out[n]); g = batch[n]; }
        #pragma unroll
        for (int d = 1; d < 32; d <<= 1) {
            float up = __shfl_up_sync(0xffffffffu, v, d);
            int gu = __shfl_up_sync(0xffffffffu, g, d);
            if (lane >= d && gu == g) v += up;
        }
        int gd = __shfl_down_sync(0xffffffffu, g, 1);
        bool last = (lane == 31) || (gd != g);
        if (n < n_nodes && last) atomicAdd(&y_out[g], v);
    }
    #undef GSYNC
}

extern "C" void kernel_launch(void* const* d_in, const int* in_sizes, int n_in,
                              void* d_out, int out_size) {
    const int*   x_idx    = (const int*)d_in[0];
    const int*   edge_src = (const int*)d_in[1];
    const int*   edge_dst = (const int*)d_in[2];
    const int*   batch    = (const int*)d_in[3];
    const float* embed    = (const float*)d_in[4];
    const float* eps0     = (const float*)d_in[5];
    const float* w1_0     = (const float*)d_in[6];
    const float* b1_0     = (const float*)d_in[7];
    const float* w2_0     = (const float*)d_in[8];
    const float* b2_0     = (const float*)d_in[9];
    const float* eps1     = (const float*)d_in[10];
    const float* w1_1     = (const float*)d_in[11];
    const float* b1_1     = (const float*)d_in[12];
    const float* w2_1     = (const float*)d_in[13];
    const float* b2_1     = (const float*)d_in[14];

    int n_nodes = in_sizes[0];
    int n_edges = in_sizes[1];
    if (n_nodes > N_NODES_MAX) n_nodes = N_NODES_MAX;
    if (n_edges > N_EDGES_MAX) n_edges = N_EDGES_MAX;

    float* out = (float*)d_out;
    float* y_out;
    float* x_out;
    int y_len;
    if (out_size >= n_nodes + 1) {     // (y_hat, x) concatenated, y first
        y_len = out_size - n_nodes;
        y_out = out;
        x_out = out + y_len;
    } else {
        y_len = out_size;
        y_out = out;
        x_out = g_xfall;
    }

    // Exact co-residency grid (deterministic; no deadlock possible)
    int dev = 0, sms = 0, mbs = 0;
    cudaGetDevice(&dev);
    cudaDeviceGetAttribute(&sms, cudaDevAttrMultiProcessorCount, dev);
    cudaOccupancyMaxActiveBlocksPerMultiprocessor(&mbs, k_main, NT, 0);
    if (mbs < 1) mbs = 1;
    if (mbs > 8) mbs = 8;
    int nb = sms * mbs;
    if (nb < VOCAB + 4) nb = VOCAB + 4;   // need blocks 0..31 for fold roles

    k_main<<<nb, NT>>>(x_idx, edge_src, edge_dst, batch,
                       embed, w1_0, b1_0, w2_0, b2_0,
                       w1_1, b1_1, w2_1, b2_1, eps0, eps1,
                       y_out, x_out, y_len, n_nodes, n_edges);
}

// round 15
// speedup vs baseline: 1.3360x; 1.3360x over previous
#include <cuda_runtime.h>

#define HID 128
#define VOCAB 28
#define N_NODES_MAX 100000
#define N_EDGES_MAX 1600000
#define FOLD_BLOCKS 32   // 28 Ep rows + b0c + Wc + scalars/y-zero

// ---- device scratch (no allocations allowed) ----
// Packed per-node histogram: 8 uint32 per node = one 32B sector.
// INVARIANT: all-zero at kernel_launch entry (zero-init at load; k_node
// re-zeroes every sector it consumes, restoring the invariant for replays).
__device__ __align__(16) unsigned g_cntp[N_NODES_MAX * 8];   // 3.2 MB
__device__ float g_Ep[VOCAB * HID];     // embed @ (w1_0 @ w2_0)
__device__ float g_b0c[HID];            // b1_0 @ w2_0 + b2_0
__device__ float g_Wc[HID];             // w1_1 @ w2_1
__device__ float g_scal[3];             // {1+eps0, 1+eps1, b1_1.w2_1 + b2_1}
__device__ float g_z1[N_NODES_MAX];     // relu(h0) . Wc per node
__device__ float g_xfall[N_NODES_MAX];  // fallback x buffer

// ---- fused: weight folding + y-zero (blocks 0..31) + edge histogram ----
__global__ void __launch_bounds__(256)
k_hist_fold(const int* __restrict__ src, const int* __restrict__ dst,
            const int* __restrict__ xidx, int n4, int n_edges,
            const float* __restrict__ embed, const float* __restrict__ w1_0,
            const float* __restrict__ b1_0,  const float* __restrict__ w2_0,
            const float* __restrict__ b2_0,  const float* __restrict__ w1_1,
            const float* __restrict__ b1_1,  const float* __restrict__ w2_1,
            const float* __restrict__ b2_1,  const float* __restrict__ eps0,
            const float* __restrict__ eps1,
            float* __restrict__ y_out, int y_len) {
    int b = blockIdx.x;
    if (b < FOLD_BLOCKS) {
        int j = threadIdx.x;
        if (j >= HID) return;
        if (b < VOCAB) {
            __shared__ float sT[HID];
            float a0 = 0.f, a1 = 0.f, a2 = 0.f, a3 = 0.f;
            #pragma unroll
            for (int m = 0; m < HID; m += 4) {
                a0 = fmaf(embed[b * HID + m + 0], w1_0[(m + 0) * HID + j], a0);
                a1 = fmaf(embed[b * HID + m + 1], w1_0[(m + 1) * HID + j], a1);
                a2 = fmaf(embed[b * HID + m + 2], w1_0[(m + 2) * HID + j], a2);
                a3 = fmaf(embed[b * HID + m + 3], w1_0[(m + 3) * HID + j], a3);
            }
            sT[j] = (a0 + a1) + (a2 + a3);
            __syncthreads();
            float c0 = 0.f, c1 = 0.f, c2 = 0.f, c3 = 0.f;
            #pragma unroll
            for (int k = 0; k < HID; k += 4) {
                c0 = fmaf(sT[k + 0], w2_0[(k + 0) * HID + j], c0);
                c1 = fmaf(sT[k + 1], w2_0[(k + 1) * HID + j], c1);
                c2 = fmaf(sT[k + 2], w2_0[(k + 2) * HID + j], c2);
                c3 = fmaf(sT[k + 3], w2_0[(k + 3) * HID + j], c3);
            }
            g_Ep[b * HID + j] = (c0 + c1) + (c2 + c3);
        } else if (b == VOCAB) {        // b0c = b1_0 @ w2_0 + b2_0
            float c0 = b2_0[j], c1 = 0.f, c2 = 0.f, c3 = 0.f;
            #pragma unroll
            for (int k = 0; k < HID; k += 4) {
                c0 = fmaf(b1_0[k + 0], w2_0[(k + 0) * HID + j], c0);
                c1 = fmaf(b1_0[k + 1], w2_0[(k + 1) * HID + j], c1);
                c2 = fmaf(b1_0[k + 2], w2_0[(k + 2) * HID + j], c2);
                c3 = fmaf(b1_0[k + 3], w2_0[(k + 3) * HID + j], c3);
            }
            g_b0c[j] = (c0 + c1) + (c2 + c3);
        } else if (b == VOCAB + 1) {    // Wc = w1_1 @ w2_1
            float c0 = 0.f, c1 = 0.f, c2 = 0.f, c3 = 0.f;
            #pragma unroll
            for (int k = 0; k < HID; k += 4) {
                c0 = fmaf(w1_1[j * HID + k + 0], w2_1[k + 0], c0);
                c1 = fmaf(w1_1[j * HID + k + 1], w2_1[k + 1], c1);
                c2 = fmaf(w1_1[j * HID + k + 2], w2_1[k + 2], c2);
                c3 = fmaf(w1_1[j * HID + k + 3], w2_1[k + 3], c3);
            }
            g_Wc[j] = (c0 + c1) + (c2 + c3);
        } else {                        // scalars + zero y_out
            if (j == 0) {
                float bc = b2_1[0];
                for (int jj = 0; jj < HID; jj++) bc = fmaf(b1_1[jj], w2_1[jj], bc);
                g_scal[0] = 1.f + eps0[0];
                g_scal[1] = 1.f + eps1[0];
                g_scal[2] = bc;
            }
            for (int i = j; i < y_len; i += HID) y_out[i] = 0.f;
        }
        return;
    }
    // ---- histogram: 4 edges/thread (proven shape) ----
    int i = (b - FOLD_BLOCKS) * blockDim.x + threadIdx.x;
    if (i < n4) {
        int4 s = ((const int4*)src)[i];
        int4 d = ((const int4*)dst)[i];
        int t0 = xidx[s.x], t1 = xidx[s.y], t2 = xidx[s.z], t3 = xidx[s.w];
        atomicAdd(&g_cntp[d.x * 8 + (t0 >> 2)], 1u << ((t0 & 3) * 8));
        atomicAdd(&g_cntp[d.y * 8 + (t1 >> 2)], 1u << ((t1 & 3) * 8));
        atomicAdd(&g_cntp[d.z * 8 + (t2 >> 2)], 1u << ((t2 & 3) * 8));
        atomicAdd(&g_cntp[d.w * 8 + (t3 >> 2)], 1u << ((t3 & 3) * 8));
    }
    int e = n4 * 4 + i;
    if (e < n_edges) {
        int t = xidx[src[e]];
        atomicAdd(&g_cntp[dst[e] * 8 + (t >> 2)], 1u << ((t & 3) * 8));
    }
}

// ---- fused layer0 + z1 + x_out init; PDL secondary; ballot-compressed ----
__global__ void __launch_bounds__(256)
k_node(const int* __restrict__ xidx, float* __restrict__ x_out, int n_nodes) {
    __shared__ __align__(16) float sEp[VOCAB * HID];
    __shared__ __align__(16) float sB[HID];
    __shared__ __align__(16) float sW[HID];
    int tid = threadIdx.x;
    int lane = tid & 31;

    // Wait for hist_fold (writes g_Ep/g_b0c/g_Wc/g_scal/g_cntp) to complete.
    cudaGridDependencySynchronize();

    for (int i = tid; i < VOCAB * HID; i += 256) sEp[i] = g_Ep[i];
    if (tid < HID) { sB[tid] = g_b0c[tid]; sW[tid] = g_Wc[tid]; }
    __syncthreads();

    float eps0p = g_scal[0], eps1p = g_scal[1], bc = g_scal[2];
    int j0 = lane * 4;
    float4 w4 = *(const float4*)&sW[j0];
    float4 b4 = *(const float4*)&sB[j0];
    int wglob = blockIdx.x * 8 + (tid >> 5);
    int wstride = gridDim.x * 8;

    for (int node = wglob; node < n_nodes; node += wstride) {
        unsigned w = 0;
        if (lane < 8) {
            w = g_cntp[node * 8 + lane];     // one sector per node
            g_cntp[node * 8 + lane] = 0u;    // restore invariant for replay
        }
        int tn = xidx[node];
        // per-lane count for type==lane (lanes 0..27), then ballot of present types
        unsigned wsrc = __shfl_sync(0xffffffffu, w, lane >> 2);
        unsigned cl = (wsrc >> ((lane & 3) * 8)) & 255u;
        unsigned mask = __ballot_sync(0xffffffffu, (lane < VOCAB) && cl);

        float4 acc = b4;
        {
            float4 e4 = *(const float4*)&sEp[tn * HID + j0];
            acc.x = fmaf(eps0p, e4.x, acc.x); acc.y = fmaf(eps0p, e4.y, acc.y);
            acc.z = fmaf(eps0p, e4.z, acc.z); acc.w = fmaf(eps0p, e4.w, acc.w);
        }
        while (mask) {                        // only present types (~12 avg, not 28)
            int t = __ffs(mask) - 1;
            mask &= mask - 1;
            float f = (float)__shfl_sync(0xffffffffu, cl, t);
            float4 e4 = *(const float4*)&sEp[t * HID + j0];
            acc.x = fmaf(f, e4.x, acc.x); acc.y = fmaf(f, e4.y, acc.y);
            acc.z = fmaf(f, e4.z, acc.z); acc.w = fmaf(f, e4.w, acc.w);
        }
        float s = fmaxf(acc.x, 0.f) * w4.x + fmaxf(acc.y, 0.f) * w4.y
                + fmaxf(acc.z, 0.f) * w4.z + fmaxf(acc.w, 0.f) * w4.w;
        #pragma unroll
        for (int o = 16; o > 0; o >>= 1) s += __shfl_xor_sync(0xffffffffu, s, o);
        if (lane == 0) {
            g_z1[node] = s;
            x_out[node] = fmaf(eps1p, s, bc);   // scatter adds on top
        }
    }
}

// ---- layer1 scalar scatter; PDL secondary with edge-preload prologue ----
__global__ void __launch_bounds__(256)
k_scatter(const int* __restrict__ src, const int* __restrict__ dst,
          float* __restrict__ x_out, int n4, int n_edges) {
    int i = blockIdx.x * blockDim.x + threadIdx.x;
    // Independent prologue: stream in this thread's edges while k_node drains.
    int4 s = make_int4(0, 0, 0, 0), d = make_int4(0, 0, 0, 0);
    int es = -1, ed = 0;
    bool ok = (i < n4);
    if (ok) { s = ((const int4*)src)[i]; d = ((const int4*)dst)[i]; }
    int e = n4 * 4 + i;
    if (e < n_edges) { es = src[e]; ed = dst[e]; }

    cudaGridDependencySynchronize();   // wait for g_z1 / x_out init

    if (ok) {
        float z0 = g_z1[s.x], z1v = g_z1[s.y], z2 = g_z1[s.z], z3 = g_z1[s.w];
        atomicAdd(&x_out[d.x], z0);
        atomicAdd(&x_out[d.y], z1v);
        atomicAdd(&x_out[d.z], z2);
        atomicAdd(&x_out[d.w], z3);
    }
    if (es >= 0) atomicAdd(&x_out[ed], g_z1[es]);
}

// ---- graph readout; PDL secondary with batch-preload prologue ----
__global__ void __launch_bounds__(256)
k_final(const int* __restrict__ batch, const float* __restrict__ x_out,
        float* __restrict__ y_out, int n_nodes) {
    int n = blockIdx.x * blockDim.x + threadIdx.x;
    int lane = threadIdx.x & 31;
    int g = -1;
    if (n < n_nodes) g = batch[n];      // independent prologue

    cudaGridDependencySynchronize();    // wait for completed x_out

    float v = 0.f;
    if (n < n_nodes) v = x_out[n];
    #pragma unroll
    for (int dd = 1; dd < 32; dd <<= 1) {
        float up = __shfl_up_sync(0xffffffffu, v, dd);
        int gu = __shfl_up_sync(0xffffffffu, g, dd);
        if (lane >= dd && gu == g) v += up;
    }
    int gd = __shfl_down_sync(0xffffffffu, g, 1);
    bool last = (lane == 31) || (gd != g);
    if (n < n_nodes && last) atomicAdd(&y_out[g], v);
}

extern "C" void kernel_launch(void* const* d_in, const int* in_sizes, int n_in,
                              void* d_out, int out_size) {
    const int*   x_idx    = (const int*)d_in[0];
    const int*   edge_src = (const int*)d_in[1];
    const int*   edge_dst = (const int*)d_in[2];
    const int*   batch    = (const int*)d_in[3];
    const float* embed    = (const float*)d_in[4];
    const float* eps0     = (const float*)d_in[5];
    const float* w1_0     = (const float*)d_in[6];
    const float* b1_0     = (const float*)d_in[7];
    const float* w2_0     = (const float*)d_in[8];
    const float* b2_0     = (const float*)d_in[9];
    const float* eps1     = (const float*)d_in[10];
    const float* w1_1     = (const float*)d_in[11];
    const float* b1_1     = (const float*)d_in[12];
    const float* w2_1     = (const float*)d_in[13];
    const float* b2_1     = (const float*)d_in[14];

    int n_nodes = in_sizes[0];
    int n_edges = in_sizes[1];
    if (n_nodes > N_NODES_MAX) n_nodes = N_NODES_MAX;
    if (n_edges > N_EDGES_MAX) n_edges = N_EDGES_MAX;

    float* out = (float*)d_out;
    float* y_out;
    float* x_out;
    int y_len;
    if (out_size >= n_nodes + 1) {     // (y_hat, x) concatenated, y first
        y_len = out_size - n_nodes;
        y_out = out;
        x_out = out + y_len;
    } else {
        y_len = out_size;
        y_out = out;
        x_out = g_xfall;
    }

    int n4 = n_edges >> 2;
    int eblocks = (n4 + 255) / 256;    // 4 edges per thread

    // 1) fold + y-zero + histogram (normal launch)
    k_hist_fold<<<FOLD_BLOCKS + eblocks, 256>>>(
        edge_src, edge_dst, x_idx, n4, n_edges,
        embed, w1_0, b1_0, w2_0, b2_0, w1_1, b1_1, w2_1, b2_1, eps0, eps1,
        y_out, y_len);

    // 2-4) PDL launches: overlap prologue with predecessor's tail
    cudaLaunchAttribute attr[1];
    attr[0].id = cudaLaunchAttributeProgrammaticStreamSerialization;
    attr[0].val.programmaticStreamSerializationAllowed = 1;

    cudaLaunchConfig_t cfg = {};
    cfg.blockDim = dim3(256, 1, 1);
    cfg.dynamicSmemBytes = 0;
    cfg.stream = 0;
    cfg.attrs = attr;
    cfg.numAttrs = 1;

    cfg.gridDim = dim3(592, 1, 1);
    cudaLaunchKernelEx(&cfg, k_node, x_idx, x_out, n_nodes);

    cfg.gridDim = dim3((unsigned)eblocks, 1, 1);
    cudaLaunchKernelEx(&cfg, k_scatter, edge_src, edge_dst, x_out, n4, n_edges);

    cfg.gridDim = dim3((unsigned)((n_nodes + 255) / 256), 1, 1);
    cudaLaunchKernelEx(&cfg, k_final, batch, x_out, y_out, n_nodes);
}

// round 16
// speedup vs baseline: 1.3758x; 1.0298x over previous
#include <cuda_runtime.h>

#define HID 128
#define VOCAB 28
#define N_NODES_MAX 100000
#define N_EDGES_MAX 1600000
#define FOLD_BLOCKS 32   // 28 Ep rows + b0c + Wc + scalars/y-zero

// ---- device scratch (no allocations allowed) ----
// Packed per-node histogram: 8 uint32 per node = one 32B sector.
// INVARIANT: all-zero at kernel_launch entry (zero-init at load; k_node
// re-zeroes every sector it consumes, restoring the invariant for replays).
__device__ __align__(16) unsigned g_cntp[N_NODES_MAX * 8];   // 3.2 MB
__device__ float g_Ep[VOCAB * HID];     // embed @ (w1_0 @ w2_0)
__device__ float g_b0c[HID];            // b1_0 @ w2_0 + b2_0
__device__ float g_Wc[HID];             // w1_1 @ w2_1
__device__ float g_scal[3];             // {1+eps0, 1+eps1, b1_1.w2_1 + b2_1}
__device__ float g_z1[N_NODES_MAX];     // relu(h0) . Wc per node
__device__ float g_xfall[N_NODES_MAX];  // fallback x buffer

// ---- fused: weight folding + y-zero (blocks 0..31) + edge histogram ----
// Histogram: 8 edges/thread via two front-batched int4 groups (i, i+half).
__global__ void __launch_bounds__(256)
k_hist_fold(const int* __restrict__ src, const int* __restrict__ dst,
            const int* __restrict__ xidx, int n4, int half, int n_edges,
            const float* __restrict__ embed, const float* __restrict__ w1_0,
            const float* __restrict__ b1_0,  const float* __restrict__ w2_0,
            const float* __restrict__ b2_0,  const float* __restrict__ w1_1,
            const float* __restrict__ b1_1,  const float* __restrict__ w2_1,
            const float* __restrict__ b2_1,  const float* __restrict__ eps0,
            const float* __restrict__ eps1,
            float* __restrict__ y_out, int y_len) {
    int b = blockIdx.x;
    if (b < FOLD_BLOCKS) {
        int j = threadIdx.x;
        if (j >= HID) return;
        if (b < VOCAB) {
            __shared__ float sT[HID];
            float a0 = 0.f, a1 = 0.f, a2 = 0.f, a3 = 0.f;
            #pragma unroll
            for (int m = 0; m < HID; m += 4) {
                a0 = fmaf(embed[b * HID + m + 0], w1_0[(m + 0) * HID + j], a0);
                a1 = fmaf(embed[b * HID + m + 1], w1_0[(m + 1) * HID + j], a1);
                a2 = fmaf(embed[b * HID + m + 2], w1_0[(m + 2) * HID + j], a2);
                a3 = fmaf(embed[b * HID + m + 3], w1_0[(m + 3) * HID + j], a3);
            }
            sT[j] = (a0 + a1) + (a2 + a3);
            __syncthreads();
            float c0 = 0.f, c1 = 0.f, c2 = 0.f, c3 = 0.f;
            #pragma unroll
            for (int k = 0; k < HID; k += 4) {
                c0 = fmaf(sT[k + 0], w2_0[(k + 0) * HID + j], c0);
                c1 = fmaf(sT[k + 1], w2_0[(k + 1) * HID + j], c1);
                c2 = fmaf(sT[k + 2], w2_0[(k + 2) * HID + j], c2);
                c3 = fmaf(sT[k + 3], w2_0[(k + 3) * HID + j], c3);
            }
            g_Ep[b * HID + j] = (c0 + c1) + (c2 + c3);
        } else if (b == VOCAB) {        // b0c = b1_0 @ w2_0 + b2_0
            float c0 = b2_0[j], c1 = 0.f, c2 = 0.f, c3 = 0.f;
            #pragma unroll
            for (int k = 0; k < HID; k += 4) {
                c0 = fmaf(b1_0[k + 0], w2_0[(k + 0) * HID + j], c0);
                c1 = fmaf(b1_0[k + 1], w2_0[(k + 1) * HID + j], c1);
                c2 = fmaf(b1_0[k + 2], w2_0[(k + 2) * HID + j], c2);
                c3 = fmaf(b1_0[k + 3], w2_0[(k + 3) * HID + j], c3);
            }
            g_b0c[j] = (c0 + c1) + (c2 + c3);
        } else if (b == VOCAB + 1) {    // Wc = w1_1 @ w2_1
            float c0 = 0.f, c1 = 0.f, c2 = 0.f, c3 = 0.f;
            #pragma unroll
            for (int k = 0; k < HID; k += 4) {
                c0 = fmaf(w1_1[j * HID + k + 0], w2_1[k + 0], c0);
                c1 = fmaf(w1_1[j * HID + k + 1], w2_1[k + 1], c1);
                c2 = fmaf(w1_1[j * HID + k + 2], w2_1[k + 2], c2);
                c3 = fmaf(w1_1[j * HID + k + 3], w2_1[k + 3], c3);
            }
            g_Wc[j] = (c0 + c1) + (c2 + c3);
        } else {                        // scalars + zero y_out
            if (j == 0) {
                float bc = b2_1[0];
                for (int jj = 0; jj < HID; jj++) bc = fmaf(b1_1[jj], w2_1[jj], bc);
                g_scal[0] = 1.f + eps0[0];
                g_scal[1] = 1.f + eps1[0];
                g_scal[2] = bc;
            }
            for (int i = j; i < y_len; i += HID) y_out[i] = 0.f;
        }
        return;
    }
    // ---- histogram: 8 edges/thread, explicit regs (no local arrays) ----
    int i = (b - FOLD_BLOCKS) * blockDim.x + threadIdx.x;
    int i2 = i + half;
    bool ok0 = (i < half) && (i < n4);
    bool ok1 = (i < half) && (i2 < n4);
    int4 s0, d0, s1, d1;
    if (ok0) { s0 = ((const int4*)src)[i];  d0 = ((const int4*)dst)[i]; }
    if (ok1) { s1 = ((const int4*)src)[i2]; d1 = ((const int4*)dst)[i2]; }
    int ta0, ta1, ta2, ta3, tb0, tb1, tb2, tb3;
    if (ok0) { ta0 = xidx[s0.x]; ta1 = xidx[s0.y]; ta2 = xidx[s0.z]; ta3 = xidx[s0.w]; }
    if (ok1) { tb0 = xidx[s1.x]; tb1 = xidx[s1.y]; tb2 = xidx[s1.z]; tb3 = xidx[s1.w]; }
    if (ok0) {
        atomicAdd(&g_cntp[d0.x * 8 + (ta0 >> 2)], 1u << ((ta0 & 3) * 8));
        atomicAdd(&g_cntp[d0.y * 8 + (ta1 >> 2)], 1u << ((ta1 & 3) * 8));
        atomicAdd(&g_cntp[d0.z * 8 + (ta2 >> 2)], 1u << ((ta2 & 3) * 8));
        atomicAdd(&g_cntp[d0.w * 8 + (ta3 >> 2)], 1u << ((ta3 & 3) * 8));
    }
    if (ok1) {
        atomicAdd(&g_cntp[d1.x * 8 + (tb0 >> 2)], 1u << ((tb0 & 3) * 8));
        atomicAdd(&g_cntp[d1.y * 8 + (tb1 >> 2)], 1u << ((tb1 & 3) * 8));
        atomicAdd(&g_cntp[d1.z * 8 + (tb2 >> 2)], 1u << ((tb2 & 3) * 8));
        atomicAdd(&g_cntp[d1.w * 8 + (tb3 >> 2)], 1u << ((tb3 & 3) * 8));
    }
    int e = n4 * 4 + i;
    if (e < n_edges) {
        int t = xidx[src[e]];
        atomicAdd(&g_cntp[dst[e] * 8 + (t >> 2)], 1u << ((t & 3) * 8));
    }
}

// ---- fused layer0 + z1 + x_out init; PDL secondary; 2-node interleave ----
__global__ void __launch_bounds__(256)
k_node(const int* __restrict__ xidx, float* __restrict__ x_out, int n_nodes) {
    __shared__ __align__(16) float sEp[VOCAB * HID];
    __shared__ __align__(16) float sB[HID];
    __shared__ __align__(16) float sW[HID];
    int tid = threadIdx.x;
    int lane = tid & 31;

    cudaGridDependencySynchronize();   // hist_fold wrote Ep/b0c/Wc/scal/cntp

    for (int i = tid; i < VOCAB * HID; i += 256) sEp[i] = g_Ep[i];
    if (tid < HID) { sB[tid] = g_b0c[tid]; sW[tid] = g_Wc[tid]; }
    __syncthreads();

    float eps0p = g_scal[0], eps1p = g_scal[1], bc = g_scal[2];
    int j0 = lane * 4;
    float4 w4 = *(const float4*)&sW[j0];
    float4 b4 = *(const float4*)&sB[j0];
    int wglob = blockIdx.x * 8 + (tid >> 5);
    int wstride = gridDim.x * 8;

    for (int node = wglob; node < n_nodes; node += 2 * wstride) {
        int nodeB = node + wstride;
        bool okB = (nodeB < n_nodes);
        // front-batch both nodes' counter sectors + types (hide L2 latency)
        unsigned wA = 0, wB = 0;
        if (lane < 8) {
            wA = g_cntp[node * 8 + lane];
            g_cntp[node * 8 + lane] = 0u;            // restore invariant
            if (okB) {
                wB = g_cntp[nodeB * 8 + lane];
                g_cntp[nodeB * 8 + lane] = 0u;
            }
        }
        int tnA = xidx[node];
        int tnB = okB ? xidx[nodeB] : 0;

        unsigned wsA = __shfl_sync(0xffffffffu, wA, lane >> 2);
        unsigned clA = (wsA >> ((lane & 3) * 8)) & 255u;
        unsigned mA = __ballot_sync(0xffffffffu, (lane < VOCAB) && clA);
        unsigned wsB = __shfl_sync(0xffffffffu, wB, lane >> 2);
        unsigned clB = (wsB >> ((lane & 3) * 8)) & 255u;
        unsigned mB = __ballot_sync(0xffffffffu, (lane < VOCAB) && clB);

        float4 aA = b4, aB = b4;
        {
            float4 e4 = *(const float4*)&sEp[tnA * HID + j0];
            aA.x = fmaf(eps0p, e4.x, aA.x); aA.y = fmaf(eps0p, e4.y, aA.y);
            aA.z = fmaf(eps0p, e4.z, aA.z); aA.w = fmaf(eps0p, e4.w, aA.w);
        }
        if (okB) {
            float4 e4 = *(const float4*)&sEp[tnB * HID + j0];
            aB.x = fmaf(eps0p, e4.x, aB.x); aB.y = fmaf(eps0p, e4.y, aB.y);
            aB.z = fmaf(eps0p, e4.z, aB.z); aB.w = fmaf(eps0p, e4.w, aB.w);
        }
        while (mA) {
            int t = __ffs(mA) - 1; mA &= mA - 1;
            float f = (float)__shfl_sync(0xffffffffu, clA, t);
            float4 e4 = *(const float4*)&sEp[t * HID + j0];
            aA.x = fmaf(f, e4.x, aA.x); aA.y = fmaf(f, e4.y, aA.y);
            aA.z = fmaf(f, e4.z, aA.z); aA.w = fmaf(f, e4.w, aA.w);
        }
        while (mB) {
            int t = __ffs(mB) - 1; mB &= mB - 1;
            float f = (float)__shfl_sync(0xffffffffu, clB, t);
            float4 e4 = *(const float4*)&sEp[t * HID + j0];
            aB.x = fmaf(f, e4.x, aB.x); aB.y = fmaf(f, e4.y, aB.y);
            aB.z = fmaf(f, e4.z, aB.z); aB.w = fmaf(f, e4.w, aB.w);
        }
        float sA = fmaxf(aA.x, 0.f) * w4.x + fmaxf(aA.y, 0.f) * w4.y
                 + fmaxf(aA.z, 0.f) * w4.z + fmaxf(aA.w, 0.f) * w4.w;
        float sB2 = fmaxf(aB.x, 0.f) * w4.x + fmaxf(aB.y, 0.f) * w4.y
                  + fmaxf(aB.z, 0.f) * w4.z + fmaxf(aB.w, 0.f) * w4.w;
        #pragma unroll
        for (int o = 16; o > 0; o >>= 1) {
            sA += __shfl_xor_sync(0xffffffffu, sA, o);
            sB2 += __shfl_xor_sync(0xffffffffu, sB2, o);
        }
        if (lane == 0) {
            g_z1[node] = sA;
            x_out[node] = fmaf(eps1p, sA, bc);
            if (okB) {
                g_z1[nodeB] = sB2;
                x_out[nodeB] = fmaf(eps1p, sB2, bc);
            }
        }
    }
}

// ---- layer1 scalar scatter; PDL; 8 edges/thread, explicit regs ----
__global__ void __launch_bounds__(256)
k_scatter(const int* __restrict__ src, const int* __restrict__ dst,
          float* __restrict__ x_out, int n4, int half, int n_edges) {
    int i = blockIdx.x * blockDim.x + threadIdx.x;
    int i2 = i + half;
    bool ok0 = (i < half) && (i < n4);
    bool ok1 = (i < half) && (i2 < n4);
    // Independent prologue: stream edges while k_node drains.
    int4 s0, d0, s1, d1;
    if (ok0) { s0 = ((const int4*)src)[i];  d0 = ((const int4*)dst)[i]; }
    if (ok1) { s1 = ((const int4*)src)[i2]; d1 = ((const int4*)dst)[i2]; }
    int es = -1, ed = 0;
    int e = n4 * 4 + i;
    if (e < n_edges) { es = src[e]; ed = dst[e]; }

    cudaGridDependencySynchronize();   // wait for g_z1 / x_out init

    float za0, za1, za2, za3, zb0, zb1, zb2, zb3;
    if (ok0) { za0 = g_z1[s0.x]; za1 = g_z1[s0.y]; za2 = g_z1[s0.z]; za3 = g_z1[s0.w]; }
    if (ok1) { zb0 = g_z1[s1.x]; zb1 = g_z1[s1.y]; zb2 = g_z1[s1.z]; zb3 = g_z1[s1.w]; }
    if (ok0) {
        atomicAdd(&x_out[d0.x], za0);
        atomicAdd(&x_out[d0.y], za1);
        atomicAdd(&x_out[d0.z], za2);
        atomicAdd(&x_out[d0.w], za3);
    }
    if (ok1) {
        atomicAdd(&x_out[d1.x], zb0);
        atomicAdd(&x_out[d1.y], zb1);
        atomicAdd(&x_out[d1.z], zb2);
        atomicAdd(&x_out[d1.w], zb3);
    }
    if (es >= 0) atomicAdd(&x_out[ed], g_z1[es]);
}

// ---- graph readout; PDL secondary with batch-preload prologue ----
__global__ void __launch_bounds__(256)
k_final(const int* __restrict__ batch, const float* __restrict__ x_out,
        float* __restrict__ y_out, int n_nodes) {
    int n = blockIdx.x * blockDim.x + threadIdx.x;
    int lane = threadIdx.x & 31;
    int g = -1;
    if (n < n_nodes) g = batch[n];      // independent prologue

    cudaGridDependencySynchronize();    // wait for completed x_out

    float v = 0.f;
    if (n < n_nodes) v = x_out[n];
    #pragma unroll
    for (int dd = 1; dd < 32; dd <<= 1) {
        float up = __shfl_up_sync(0xffffffffu, v, dd);
        int gu = __shfl_up_sync(0xffffffffu, g, dd);
        if (lane >= dd && gu == g) v += up;
    }
    int gd = __shfl_down_sync(0xffffffffu, g, 1);
    bool last = (lane == 31) || (gd != g);
    if (n < n_nodes && last) atomicAdd(&y_out[g], v);
}

extern "C" void kernel_launch(void* const* d_in, const int* in_sizes, int n_in,
                              void* d_out, int out_size) {
    const int*   x_idx    = (const int*)d_in[0];
    const int*   edge_src = (const int*)d_in[1];
    const int*   edge_dst = (const int*)d_in[2];
    const int*   batch    = (const int*)d_in[3];
    const float* embed    = (const float*)d_in[4];
    const float* eps0     = (const float*)d_in[5];
    const float* w1_0     = (const float*)d_in[6];
    const float* b1_0     = (const float*)d_in[7];
    const float* w2_0     = (const float*)d_in[8];
    const float* b2_0     = (const float*)d_in[9];
    const float* eps1     = (const float*)d_in[10];
    const float* w1_1     = (const float*)d_in[11];
    const float* b1_1     = (const float*)d_in[12];
    const float* w2_1     = (const float*)d_in[13];
    const float* b2_1     = (const float*)d_in[14];

    int n_nodes = in_sizes[0];
    int n_edges = in_sizes[1];
    if (n_nodes > N_NODES_MAX) n_nodes = N_NODES_MAX;
    if (n_edges > N_EDGES_MAX) n_edges = N_EDGES_MAX;

    float* out = (float*)d_out;
    float* y_out;
    float* x_out;
    int y_len;
    if (out_size >= n_nodes + 1) {     // (y_hat, x) concatenated, y first
        y_len = out_size - n_nodes;
        y_out = out;
        x_out = out + y_len;
    } else {
        y_len = out_size;
        y_out = out;
        x_out = g_xfall;
    }

    int n4 = n_edges >> 2;             // int4 edge groups
    int half = (n4 + 1) >> 1;          // 8 edges/thread: groups i and i+half
    int eblocks = (half + 255) / 256;

    // 1) fold + y-zero + histogram (normal launch)
    k_hist_fold<<<FOLD_BLOCKS + eblocks, 256>>>(
        edge_src, edge_dst, x_idx, n4, half, n_edges,
        embed, w1_0, b1_0, w2_0, b2_0, w1_1, b1_1, w2_1, b2_1, eps0, eps1,
        y_out, y_len);

    // 2-4) PDL launches: overlap prologue with predecessor's tail
    cudaLaunchAttribute attr[1];
    attr[0].id = cudaLaunchAttributeProgrammaticStreamSerialization;
    attr[0].val.programmaticStreamSerializationAllowed = 1;

    cudaLaunchConfig_t cfg = {};
    cfg.blockDim = dim3(256, 1, 1);
    cfg.dynamicSmemBytes = 0;
    cfg.stream = 0;
    cfg.attrs = attr;
    cfg.numAttrs = 1;

    cfg.gridDim = dim3(592, 1, 1);
    cudaLaunchKernelEx(&cfg, k_node, x_idx, x_out, n_nodes);

    cfg.gridDim = dim3((unsigned)eblocks, 1, 1);
    cudaLaunchKernelEx(&cfg, k_scatter, edge_src, edge_dst, x_out, n4, half, n_edges);

    cfg.gridDim = dim3((unsigned)((n_nodes + 255) / 256), 1, 1);
    cudaLaunchKernelEx(&cfg, k_final, batch, x_out, y_out, n_nodes);
}